// round 1
// baseline (speedup 1.0000x reference)
#include <cuda_runtime.h>
#include <math.h>

// Problem dims
#define Bn   64
#define Tn   1024
#define TWOK 512
#define En   128
#define Hh   256
#define FH   1024          // 4*H
#define BT   (Bn*Tn)       // 65536
#define KXC  264           // 2E+1 padded to multiple of 8

// ---------------- scratch (static device globals; no runtime allocation) ----------------
__device__ float g_s[BT];                          // per-(b,t) feature sum
__device__ float g_cl[(size_t)BT * TWOK];          // log1p(counts)      134 MB
__device__ float g_xc[(size_t)BT * KXC];           // [ex | ec | ed | 0]  69 MB
__device__ float g_WlP[KXC * FH];                  // padded+col-permuted Wl
__device__ float g_blP[FH];                        // permuted bl
__device__ float g_pre[(size_t)BT * FH];           // LSTM input preacts (permuted cols) 268 MB
__device__ float g_H[(size_t)BT * Hh];             // LSTM hidden history  67 MB
__device__ float g_Y[(size_t)BT * Hh];             // sigmoid(h@Wo+bo)*q   67 MB
__device__ int   g_bar;                            // grid barrier counter

// ---------------- tiny kernels ----------------
__global__ void k_reset() { g_bar = 0; }

// s[b,t] = sum_f x[b,t,f]   (one warp per row)
__global__ void k_sums(const float* __restrict__ x) {
    int row  = blockIdx.x * 8 + (threadIdx.x >> 5);
    int lane = threadIdx.x & 31;
    const float4* xr = (const float4*)(x + (size_t)row * TWOK);
    float s = 0.f;
#pragma unroll
    for (int i = 0; i < 4; i++) {
        float4 v = xr[i * 32 + lane];
        s += v.x + v.y + v.z + v.w;
    }
#pragma unroll
    for (int o = 16; o; o >>= 1) s += __shfl_xor_sync(0xffffffffu, s, o);
    if (!lane) g_s[row] = s;
}

// exp_delta -> xc[:,256]; zero the pad columns 257..263
__global__ void k_delta(const float* __restrict__ delta,
                        const float* __restrict__ Wd,
                        const float* __restrict__ bd) {
    int i = blockIdx.x * 256 + threadIdx.x;  // [0, BT)
    float ed = expf(-(delta[i] * Wd[0] + bd[0]));
    float* xr = g_xc + (size_t)i * KXC;
    xr[256] = ed;
#pragma unroll
    for (int j = 257; j < KXC; j++) xr[j] = 0.f;
}

// count scan: c_t = s_t * c_{t-1} + x_t, per (b, feature) chain; write log1p
__global__ void k_scan(const float* __restrict__ x) {
    int gidx = blockIdx.x * 256 + threadIdx.x;   // 32768 chains
    int b = gidx >> 9, f = gidx & 511;
    const float* xp = x    + (size_t)b * Tn * TWOK + f;
    float*       cp = g_cl + (size_t)b * Tn * TWOK + f;
    const float* sp = g_s + b * Tn;
    float c = 0.f;
    for (int t = 0; t < Tn; t++) {
        c = fmaf(sp[t], c, xp[(size_t)t * TWOK]);
        cp[(size_t)t * TWOK] = log1pf(c);
    }
}

// Build padded, gate-permuted Wl (rows 257..263 zero) and permuted bl.
// permuted col jp = unit*4 + gate  <->  orig col = gate*256 + unit
__global__ void k_wlp(const float* __restrict__ Wl, const float* __restrict__ bl) {
    int i = blockIdx.x * 256 + threadIdx.x;      // KXC*FH = 270336
    if (i >= KXC * FH) return;
    int k = i / FH, jp = i % FH;
    int orig = (jp & 3) * 256 + (jp >> 2);
    g_WlP[i] = (k < 2 * En + 1) ? Wl[k * FH + orig] : 0.f;
    if (k == 0) g_blP[jp] = bl[orig];
}

// ---------------- generic fp32 SGEMM: C[r, coff+c] = epi(A@B + bias) ----------------
// BM=BN=128, BK=8, 256 threads, 8x8 microtile. M,N multiples of 128; K multiple of 8.
template <int EPI>
__global__ void __launch_bounds__(256, 2) sgemm(
    const float* __restrict__ A, int lda,
    const float* __restrict__ Bm, int ldb,
    float* __restrict__ C, int ldc, int coff,
    const float* __restrict__ bias,
    const float* __restrict__ q,
    int K) {
    __shared__ float As[8][128];
    __shared__ float Bs[8][128];
    const int row0 = blockIdx.x * 128, col0 = blockIdx.y * 128;
    const int tid = threadIdx.x;
    const int ar = tid >> 1,  ac = (tid & 1) * 4;
    const int br = tid >> 5,  bc = (tid & 31) * 4;
    const int ty = tid >> 4,  tx = tid & 15;
    const float* Ap = A + (size_t)(row0 + ar) * lda + ac;
    const float* Bp = Bm + (size_t)br * ldb + col0 + bc;

    float acc[8][8];
#pragma unroll
    for (int i = 0; i < 8; i++)
#pragma unroll
        for (int j = 0; j < 8; j++) acc[i][j] = 0.f;

    for (int k0 = 0; k0 < K; k0 += 8) {
        float4 av = *(const float4*)(Ap + k0);
        float4 bv = *(const float4*)(Bp + (size_t)k0 * ldb);
        __syncthreads();
        As[ac + 0][ar] = av.x; As[ac + 1][ar] = av.y;
        As[ac + 2][ar] = av.z; As[ac + 3][ar] = av.w;
        *(float4*)&Bs[br][bc] = bv;
        __syncthreads();
#pragma unroll
        for (int kk = 0; kk < 8; kk++) {
            float a[8], b[8];
            *(float4*)&a[0] = *(const float4*)&As[kk][ty * 8];
            *(float4*)&a[4] = *(const float4*)&As[kk][ty * 8 + 4];
            *(float4*)&b[0] = *(const float4*)&Bs[kk][tx * 8];
            *(float4*)&b[4] = *(const float4*)&Bs[kk][tx * 8 + 4];
#pragma unroll
            for (int i = 0; i < 8; i++)
#pragma unroll
                for (int j = 0; j < 8; j++) acc[i][j] = fmaf(a[i], b[j], acc[i][j]);
        }
    }

#pragma unroll
    for (int i = 0; i < 8; i++) {
        size_t r = (size_t)row0 + ty * 8 + i;
#pragma unroll
        for (int j = 0; j < 8; j++) {
            int c = col0 + tx * 8 + j;
            float v = acc[i][j] + bias[c];
            if (EPI == 1) v = q[r * 256 + c] / (1.f + expf(-v));  // sigmoid * q
            C[r * ldc + coff + c] = v;
        }
    }
}

// ---------------- persistent LSTM scan ----------------
// 128 CTAs; CTA g owns hidden units {2g, 2g+1} (8 permuted gate columns).
// Per step: load full h[64,256] (.cg), z = pre + h@Ul_slice, gates, write h, grid barrier.
__global__ void __launch_bounds__(256, 1) k_lstm(const float* __restrict__ Ul) {
    extern __shared__ float sm[];
    float(*Ut)[260] = (float(*)[260])sm;                 // 8 x 260 (transposed slice)
    float(*hs)[260] = (float(*)[260])(sm + 8 * 260);     // 64 x 260
    float(*zs)[8]   = (float(*)[8])(sm + 8 * 260 + 64 * 260); // 64 x 8

    const int g = blockIdx.x, tid = threadIdx.x;

    // load Ul slice, transposed: Ut[c][k] where c = ul*4 + gate
    for (int i = tid; i < 8 * 256; i += 256) {
        int c = i >> 8, k = i & 255;
        int col = (c & 3) * 256 + 2 * g + (c >> 2);
        Ut[c][k] = Ul[k * FH + col];
    }

    const int c  = tid & 7;
    const int bp = tid >> 3;
    const int b0 = 2 * bp, b1 = 2 * bp + 1;
    const int gb = tid >> 1, gu = tid & 1;   // gate-thread mapping (tid < 128)
    float cst = 0.f;

    for (int t = 0; t < Tn; t++) {
        // ---- stage h_{t-1} into shared ----
        if (t == 0) {
            for (int i = tid; i < 64 * 64; i += 256) {
                int b = i >> 6, k4 = i & 63;
                *(float4*)&hs[b][k4 * 4] = make_float4(0.f, 0.f, 0.f, 0.f);
            }
        } else {
            for (int i = tid; i < 64 * 64; i += 256) {
                int b = i >> 6, k4 = i & 63;
                float4 v = __ldcg((const float4*)(g_H + ((size_t)b * Tn + (t - 1)) * Hh + k4 * 4));
                *(float4*)&hs[b][k4 * 4] = v;
            }
        }
        float acc0 = g_pre[((size_t)b0 * Tn + t) * FH + 8 * g + c];
        float acc1 = g_pre[((size_t)b1 * Tn + t) * FH + 8 * g + c];
        __syncthreads();

        // ---- z = pre + h @ Ul_slice ----
#pragma unroll 8
        for (int k = 0; k < 256; k += 4) {
            float4 u  = *(const float4*)&Ut[c][k];
            float4 h0 = *(const float4*)&hs[b0][k];
            float4 h1 = *(const float4*)&hs[b1][k];
            acc0 = fmaf(u.x, h0.x, acc0); acc0 = fmaf(u.y, h0.y, acc0);
            acc0 = fmaf(u.z, h0.z, acc0); acc0 = fmaf(u.w, h0.w, acc0);
            acc1 = fmaf(u.x, h1.x, acc1); acc1 = fmaf(u.y, h1.y, acc1);
            acc1 = fmaf(u.z, h1.z, acc1); acc1 = fmaf(u.w, h1.w, acc1);
        }
        zs[b0][c] = acc0;
        zs[b1][c] = acc1;
        __syncthreads();

        // ---- gates + state update (128 threads: one (b, unit) each) ----
        if (tid < 128) {
            float zi = zs[gb][gu * 4 + 0];
            float zf = zs[gb][gu * 4 + 1];
            float zg = zs[gb][gu * 4 + 2];
            float zo = zs[gb][gu * 4 + 3];
            float ig = 1.f / (1.f + expf(-zi));
            float fg = 1.f / (1.f + expf(-zf));
            float gg = tanhf(zg);
            float og = 1.f / (1.f + expf(-zo));
            cst = fg * cst + ig * gg;
            float h = og * tanhf(cst);
            __stcg(g_H + ((size_t)gb * Tn + t) * Hh + 2 * g + gu, h);
            __threadfence();   // writer-side release
        }
        __syncthreads();

        // ---- grid barrier (monotonic counter; reset per launch by k_reset) ----
        if (tid == 0) {
            atomicAdd(&g_bar, 1);
            int target = 128 * (t + 1);
            while (*((volatile int*)&g_bar) < target) { }
            __threadfence();   // reader-side acquire
        }
        __syncthreads();
    }
}

// out[row] = sum_c Y[row, c]   (one warp per row)
__global__ void k_rowsum(float* __restrict__ out) {
    int row  = blockIdx.x * 8 + (threadIdx.x >> 5);
    int lane = threadIdx.x & 31;
    const float4* yr = (const float4*)(g_Y + (size_t)row * Hh);
    float4 a = yr[lane], b = yr[lane + 32];
    float s = a.x + a.y + a.z + a.w + b.x + b.y + b.z + b.w;
#pragma unroll
    for (int o = 16; o; o >>= 1) s += __shfl_xor_sync(0xffffffffu, s, o);
    if (!lane) out[row] = s;
}

// ---------------- launch ----------------
extern "C" void kernel_launch(void* const* d_in, const int* in_sizes, int n_in,
                              void* d_out, int out_size) {
    const float* x     = (const float*)d_in[0];
    const float* delta = (const float*)d_in[1];
    const float* q     = (const float*)d_in[2];
    const float* Wx    = (const float*)d_in[3];
    const float* bx    = (const float*)d_in[4];
    const float* Wc    = (const float*)d_in[5];
    const float* bc    = (const float*)d_in[6];
    const float* Wd    = (const float*)d_in[7];
    const float* bd    = (const float*)d_in[8];
    const float* Wl    = (const float*)d_in[9];
    const float* Ul    = (const float*)d_in[10];
    const float* bl    = (const float*)d_in[11];
    const float* Wo    = (const float*)d_in[12];
    const float* bo    = (const float*)d_in[13];
    float* out = (float*)d_out;

    const int SMEM_LSTM = (8 * 260 + 64 * 260 + 64 * 8) * 4;  // 76928 B
    cudaFuncSetAttribute(k_lstm, cudaFuncAttributeMaxDynamicSharedMemorySize, SMEM_LSTM);

    float *p_xc, *p_cl, *p_pre, *p_H, *p_Y, *p_WlP, *p_blP;
    cudaGetSymbolAddress((void**)&p_xc,  g_xc);
    cudaGetSymbolAddress((void**)&p_cl,  g_cl);
    cudaGetSymbolAddress((void**)&p_pre, g_pre);
    cudaGetSymbolAddress((void**)&p_H,   g_H);
    cudaGetSymbolAddress((void**)&p_Y,   g_Y);
    cudaGetSymbolAddress((void**)&p_WlP, g_WlP);
    cudaGetSymbolAddress((void**)&p_blP, g_blP);

    k_reset<<<1, 1>>>();
    k_sums<<<BT / 8, 256>>>(x);
    k_delta<<<BT / 256, 256>>>(delta, Wd, bd);
    k_scan<<<128, 256>>>(x);
    k_wlp<<<(KXC * FH + 255) / 256, 256>>>(Wl, bl);

    // embed_x -> xc[:, 0:128]
    sgemm<0><<<dim3(BT / 128, 1), 256>>>(x, TWOK, Wx, En, p_xc, KXC, 0, bx, nullptr, TWOK);
    // embed_count -> xc[:, 128:256]
    sgemm<0><<<dim3(BT / 128, 1), 256>>>(p_cl, TWOK, Wc, En, p_xc, KXC, 128, bc, nullptr, TWOK);
    // pre = xc @ WlP + blP  (gate-permuted columns)
    sgemm<0><<<dim3(BT / 128, FH / 128), 256>>>(p_xc, KXC, p_WlP, FH, p_pre, FH, 0, p_blP, nullptr, KXC);

    // sequential LSTM scan (persistent, 128 co-resident CTAs)
    k_lstm<<<128, 256, SMEM_LSTM>>>(Ul);

    // Y = sigmoid(H @ Wo + bo) * q
    sgemm<1><<<dim3(BT / 128, Hh / 128), 256>>>(p_H, Hh, Wo, Hh, p_Y, Hh, 0, bo, q, Hh);
    // out = rowsum(Y)
    k_rowsum<<<BT / 8, 256>>>(out);
}

// round 2
// speedup vs baseline: 1.0043x; 1.0043x over previous
#include <cuda_runtime.h>
#include <math.h>

// Problem dims
#define Bn   64
#define Tn   1024
#define TWOK 512
#define En   128
#define Hh   256
#define FH   1024          // 4*H
#define BT   (Bn*Tn)       // 65536
#define KXC  264           // 2E+1 padded to multiple of 8

// ---------------- packed fp32x2 helpers ----------------
__device__ __forceinline__ void fma2(unsigned long long& acc,
                                     unsigned long long a,
                                     unsigned long long b) {
    asm("fma.rn.f32x2 %0, %1, %2, %0;" : "+l"(acc) : "l"(a), "l"(b));
}
__device__ __forceinline__ float2 unpk(unsigned long long v) {
    float2 r;
    asm("mov.b64 {%0, %1}, %2;" : "=f"(r.x), "=f"(r.y) : "l"(v));
    return r;
}

// ---------------- scratch (static device globals) ----------------
__device__ float g_s[BT];                          // per-(b,t) feature sum
__device__ float g_Q[Bn * 8 * TWOK];               // segment scan partials
__device__ float g_Cin[Bn * 8 * TWOK];             // segment entry carries
__device__ float g_P[Bn * 8];                      // segment products of s
__device__ float g_cl[(size_t)BT * TWOK];          // log1p(counts)
__device__ float g_xc[(size_t)BT * KXC];           // [ex | ec | ed | 0]
__device__ float g_WlP[KXC * FH];                  // padded+col-permuted Wl
__device__ float g_blP[FH];
__device__ float g_pre[(size_t)BT * FH];           // LSTM preacts (permuted)
__device__ float g_H[(size_t)BT * Hh];             // LSTM hidden history
__device__ float g_Y[(size_t)BT * Hh];             // sigmoid(h@Wo+bo)*q
__device__ int   g_bar;

// ---------------- tiny kernels ----------------
__global__ void k_reset() { g_bar = 0; }

__global__ void k_sums(const float* __restrict__ x) {
    int row  = blockIdx.x * 8 + (threadIdx.x >> 5);
    int lane = threadIdx.x & 31;
    const float4* xr = (const float4*)(x + (size_t)row * TWOK);
    float s = 0.f;
#pragma unroll
    for (int i = 0; i < 4; i++) {
        float4 v = xr[i * 32 + lane];
        s += v.x + v.y + v.z + v.w;
    }
#pragma unroll
    for (int o = 16; o; o >>= 1) s += __shfl_xor_sync(0xffffffffu, s, o);
    if (!lane) g_s[row] = s;
}

__global__ void k_delta(const float* __restrict__ delta,
                        const float* __restrict__ Wd,
                        const float* __restrict__ bd) {
    int i = blockIdx.x * 256 + threadIdx.x;
    float ed = expf(-(delta[i] * Wd[0] + bd[0]));
    float* xr = g_xc + (size_t)i * KXC;
    xr[256] = ed;
#pragma unroll
    for (int j = 257; j < KXC; j++) xr[j] = 0.f;
}

// ----- segmented count scan: 8 segments x 128 steps -----
__global__ void k_scanA(const float* __restrict__ x) {
    int idx = blockIdx.x * 256 + threadIdx.x;     // 262144
    int f = idx & 511, seg = (idx >> 9) & 7, b = idx >> 12;
    const float* sp = g_s + b * Tn + seg * 128;
    const float* xp = x + ((size_t)b * Tn + seg * 128) * TWOK + f;
    float c = 0.f;
    for (int tt = 0; tt < 128; tt++)
        c = fmaf(sp[tt], c, xp[(size_t)tt * TWOK]);
    g_Q[idx] = c;
}
__global__ void k_P() {
    int idx = blockIdx.x * 256 + threadIdx.x;     // 512
    if (idx >= Bn * 8) return;
    int b = idx >> 3, seg = idx & 7;
    const float* sp = g_s + b * Tn + seg * 128;
    float p = 1.f;
    for (int tt = 0; tt < 128; tt++) p *= sp[tt];
    g_P[idx] = p;
}
__global__ void k_carry() {
    int idx = blockIdx.x * 256 + threadIdx.x;     // 32768
    int b = idx >> 9, f = idx & 511;
    float c = 0.f;
#pragma unroll
    for (int j = 0; j < 8; j++) {
        int qi = (b * 8 + j) * 512 + f;
        g_Cin[qi] = c;
        c = g_P[b * 8 + j] * c + g_Q[qi];
    }
}
__global__ void k_scanC(const float* __restrict__ x) {
    int idx = blockIdx.x * 256 + threadIdx.x;     // 262144
    int f = idx & 511, seg = (idx >> 9) & 7, b = idx >> 12;
    const float* sp = g_s + b * Tn + seg * 128;
    const float* xp = x    + ((size_t)b * Tn + seg * 128) * TWOK + f;
    float*       cp = g_cl + ((size_t)b * Tn + seg * 128) * TWOK + f;
    float c = g_Cin[idx];
    for (int tt = 0; tt < 128; tt++) {
        c = fmaf(sp[tt], c, xp[(size_t)tt * TWOK]);
        cp[(size_t)tt * TWOK] = log1pf(c);
    }
}

// Build padded, gate-permuted Wl and permuted bl.
__global__ void k_wlp(const float* __restrict__ Wl, const float* __restrict__ bl) {
    int i = blockIdx.x * 256 + threadIdx.x;
    if (i >= KXC * FH) return;
    int k = i / FH, jp = i % FH;
    int orig = (jp & 3) * 256 + (jp >> 2);
    g_WlP[i] = (k < 2 * En + 1) ? Wl[k * FH + orig] : 0.f;
    if (k == 0) g_blP[jp] = bl[orig];
}

// ---------------- fp32x2 SGEMM: C[r, coff+c] = epi(A@B + bias) ----------------
// BM=BN=128, BK=8, 256 threads, 8x8 microtile, even/odd-k packed FFMA2,
// register-prefetch + double-buffered smem.
template <int EPI>
__global__ void __launch_bounds__(256, 1) sgemm(
    const float* __restrict__ A, int lda,
    const float* __restrict__ Bm, int ldb,
    float* __restrict__ C, int ldc, int coff,
    const float* __restrict__ bias,
    const float* __restrict__ q,
    int K) {
    __shared__ __align__(16) float2 As2[2][4][128];
    __shared__ __align__(16) float2 Bs2[2][4][128];
    const int row0 = blockIdx.x * 128, col0 = blockIdx.y * 128;
    const int tid = threadIdx.x;
    // A staging: thread -> (row ar, quad aq)
    const int ar = tid >> 1, aq = tid & 1;
    // B staging: warp w handles k-pair plane bk2, half-columns
    const int w = tid >> 5, lane = tid & 31;
    const int bk2 = w >> 1, bc = (w & 1) * 64 + lane * 2;
    // compute mapping
    const int ty = tid >> 4, tx = tid & 15;

    const float* Ap  = A + (size_t)(row0 + ar) * lda + aq * 4;
    const float* Bp0 = Bm + col0 + bc;

    unsigned long long acc[8][8];
#pragma unroll
    for (int i = 0; i < 8; i++)
#pragma unroll
        for (int j = 0; j < 8; j++) acc[i][j] = 0ull;

    // prologue: stage tile 0
    {
        float4 av = *(const float4*)Ap;
        float2 b0 = *(const float2*)(Bp0 + (size_t)(2 * bk2) * ldb);
        float2 b1 = *(const float2*)(Bp0 + (size_t)(2 * bk2 + 1) * ldb);
        As2[0][2 * aq][ar]     = make_float2(av.x, av.y);
        As2[0][2 * aq + 1][ar] = make_float2(av.z, av.w);
        *(float4*)&Bs2[0][bk2][bc] = make_float4(b0.x, b1.x, b0.y, b1.y);
    }
    __syncthreads();

    int buf = 0;
    for (int k0 = 0; k0 < K; k0 += 8) {
        const bool more = (k0 + 8 < K);
        float4 avn; float2 b0n, b1n;
        if (more) {
            avn = *(const float4*)(Ap + k0 + 8);
            b0n = *(const float2*)(Bp0 + (size_t)(k0 + 8 + 2 * bk2) * ldb);
            b1n = *(const float2*)(Bp0 + (size_t)(k0 + 8 + 2 * bk2 + 1) * ldb);
        }
#pragma unroll
        for (int kk2 = 0; kk2 < 4; kk2++) {
            ulonglong2 a01 = *(const ulonglong2*)&As2[buf][kk2][ty * 8];
            ulonglong2 a23 = *(const ulonglong2*)&As2[buf][kk2][ty * 8 + 2];
            ulonglong2 a45 = *(const ulonglong2*)&As2[buf][kk2][ty * 8 + 4];
            ulonglong2 a67 = *(const ulonglong2*)&As2[buf][kk2][ty * 8 + 6];
            ulonglong2 b01 = *(const ulonglong2*)&Bs2[buf][kk2][tx * 8];
            ulonglong2 b23 = *(const ulonglong2*)&Bs2[buf][kk2][tx * 8 + 2];
            ulonglong2 b45 = *(const ulonglong2*)&Bs2[buf][kk2][tx * 8 + 4];
            ulonglong2 b67 = *(const ulonglong2*)&Bs2[buf][kk2][tx * 8 + 6];
            unsigned long long aa[8] = {a01.x, a01.y, a23.x, a23.y,
                                        a45.x, a45.y, a67.x, a67.y};
            unsigned long long bb[8] = {b01.x, b01.y, b23.x, b23.y,
                                        b45.x, b45.y, b67.x, b67.y};
#pragma unroll
            for (int i = 0; i < 8; i++)
#pragma unroll
                for (int j = 0; j < 8; j++) fma2(acc[i][j], aa[i], bb[j]);
        }
        if (more) {
            As2[buf ^ 1][2 * aq][ar]     = make_float2(avn.x, avn.y);
            As2[buf ^ 1][2 * aq + 1][ar] = make_float2(avn.z, avn.w);
            *(float4*)&Bs2[buf ^ 1][bk2][bc] = make_float4(b0n.x, b1n.x, b0n.y, b1n.y);
        }
        __syncthreads();
        buf ^= 1;
    }

#pragma unroll
    for (int i = 0; i < 8; i++) {
        size_t r = (size_t)row0 + ty * 8 + i;
#pragma unroll
        for (int j = 0; j < 8; j++) {
            int c = col0 + tx * 8 + j;
            float2 p = unpk(acc[i][j]);
            float v = p.x + p.y + bias[c];
            if (EPI == 1) v = q[r * 256 + c] / (1.f + expf(-v));
            C[r * ldc + coff + c] = v;
        }
    }
}

// ---------------- persistent LSTM scan ----------------
// 128 CTAs; CTA g owns hidden units {2g, 2g+1} (8 permuted gate columns).
__global__ void __launch_bounds__(256, 1) k_lstm(const float* __restrict__ Ul) {
    extern __shared__ float sm[];
    float(*Ut)[260] = (float(*)[260])sm;                       // 8 x 260
    float(*hs)[260] = (float(*)[260])(sm + 8 * 260);           // 64 x 260
    float(*zs)[8]   = (float(*)[8])(sm + 8 * 260 + 64 * 260);  // 64 x 8

    const int g = blockIdx.x, tid = threadIdx.x;

    for (int i = tid; i < 8 * 256; i += 256) {
        int c = i >> 8, k = i & 255;
        int col = (c & 3) * 256 + 2 * g + (c >> 2);
        Ut[c][k] = Ul[k * FH + col];
    }

    const int c  = tid & 7;
    const int bp = tid >> 3;
    const int b0 = 2 * bp, b1 = 2 * bp + 1;
    const int gb = tid >> 1, gu = tid & 1;
    float cst = 0.f;
    int* barp = &g_bar;

    for (int t = 0; t < Tn; t++) {
        // ---- stage h_{t-1} into shared ----
        if (t == 0) {
            for (int i = tid; i < 64 * 64; i += 256) {
                int b = i >> 6, k4 = i & 63;
                *(float4*)&hs[b][k4 * 4] = make_float4(0.f, 0.f, 0.f, 0.f);
            }
        } else {
            for (int i = tid; i < 64 * 64; i += 256) {
                int b = i >> 6, k4 = i & 63;
                float4 v = __ldcg((const float4*)(g_H + ((size_t)b * Tn + (t - 1)) * Hh + k4 * 4));
                *(float4*)&hs[b][k4 * 4] = v;
            }
        }
        float pre0 = g_pre[((size_t)b0 * Tn + t) * FH + 8 * g + c];
        float pre1 = g_pre[((size_t)b1 * Tn + t) * FH + 8 * g + c];
        __syncthreads();

        // ---- z = pre + h @ Ul_slice  (even/odd-k packed) ----
        unsigned long long acc0 = 0ull, acc1 = 0ull;
#pragma unroll 8
        for (int k = 0; k < 256; k += 4) {
            ulonglong2 u  = *(const ulonglong2*)&Ut[c][k];
            ulonglong2 h0 = *(const ulonglong2*)&hs[b0][k];
            ulonglong2 h1 = *(const ulonglong2*)&hs[b1][k];
            fma2(acc0, u.x, h0.x); fma2(acc0, u.y, h0.y);
            fma2(acc1, u.x, h1.x); fma2(acc1, u.y, h1.y);
        }
        float2 p0 = unpk(acc0), p1 = unpk(acc1);
        zs[b0][c] = p0.x + p0.y + pre0;
        zs[b1][c] = p1.x + p1.y + pre1;
        __syncthreads();

        // ---- gates + state update ----
        if (tid < 128) {
            float zi = zs[gb][gu * 4 + 0];
            float zf = zs[gb][gu * 4 + 1];
            float zg = zs[gb][gu * 4 + 2];
            float zo = zs[gb][gu * 4 + 3];
            float ig = 1.f / (1.f + expf(-zi));
            float fg = 1.f / (1.f + expf(-zf));
            float gg = tanhf(zg);
            float og = 1.f / (1.f + expf(-zo));
            cst = fg * cst + ig * gg;
            float h = og * tanhf(cst);
            __stcg(g_H + ((size_t)gb * Tn + t) * Hh + 2 * g + gu, h);
        }
        __syncthreads();

        // ---- grid barrier: release arrival + acquire spin ----
        if (tid == 0) {
            asm volatile("red.release.gpu.global.add.s32 [%0], 1;"
                         :: "l"(barp) : "memory");
            int target = 128 * (t + 1), v;
            do {
                asm volatile("ld.acquire.gpu.global.b32 %0, [%1];"
                             : "=r"(v) : "l"(barp) : "memory");
            } while (v < target);
        }
        __syncthreads();
    }
}

__global__ void k_rowsum(float* __restrict__ out) {
    int row  = blockIdx.x * 8 + (threadIdx.x >> 5);
    int lane = threadIdx.x & 31;
    const float4* yr = (const float4*)(g_Y + (size_t)row * Hh);
    float4 a = yr[lane], b = yr[lane + 32];
    float s = a.x + a.y + a.z + a.w + b.x + b.y + b.z + b.w;
#pragma unroll
    for (int o = 16; o; o >>= 1) s += __shfl_xor_sync(0xffffffffu, s, o);
    if (!lane) out[row] = s;
}

// ---------------- launch ----------------
extern "C" void kernel_launch(void* const* d_in, const int* in_sizes, int n_in,
                              void* d_out, int out_size) {
    const float* x     = (const float*)d_in[0];
    const float* delta = (const float*)d_in[1];
    const float* q     = (const float*)d_in[2];
    const float* Wx    = (const float*)d_in[3];
    const float* bx    = (const float*)d_in[4];
    const float* Wc    = (const float*)d_in[5];
    const float* bc    = (const float*)d_in[6];
    const float* Wd    = (const float*)d_in[7];
    const float* bd    = (const float*)d_in[8];
    const float* Wl    = (const float*)d_in[9];
    const float* Ul    = (const float*)d_in[10];
    const float* bl    = (const float*)d_in[11];
    const float* Wo    = (const float*)d_in[12];
    const float* bo    = (const float*)d_in[13];
    float* out = (float*)d_out;

    const int SMEM_LSTM = (8 * 260 + 64 * 260 + 64 * 8) * 4;
    cudaFuncSetAttribute(k_lstm, cudaFuncAttributeMaxDynamicSharedMemorySize, SMEM_LSTM);

    float *p_xc, *p_cl, *p_pre, *p_H, *p_Y, *p_WlP, *p_blP;
    cudaGetSymbolAddress((void**)&p_xc,  g_xc);
    cudaGetSymbolAddress((void**)&p_cl,  g_cl);
    cudaGetSymbolAddress((void**)&p_pre, g_pre);
    cudaGetSymbolAddress((void**)&p_H,   g_H);
    cudaGetSymbolAddress((void**)&p_Y,   g_Y);
    cudaGetSymbolAddress((void**)&p_WlP, g_WlP);
    cudaGetSymbolAddress((void**)&p_blP, g_blP);

    k_reset<<<1, 1>>>();
    k_sums<<<BT / 8, 256>>>(x);
    k_delta<<<BT / 256, 256>>>(delta, Wd, bd);
    k_wlp<<<(KXC * FH + 255) / 256, 256>>>(Wl, bl);

    // segmented count scan
    k_scanA<<<1024, 256>>>(x);
    k_P<<<2, 256>>>();
    k_carry<<<128, 256>>>();
    k_scanC<<<1024, 256>>>(x);

    // embed_x -> xc[:, 0:128]
    sgemm<0><<<dim3(BT / 128, 1), 256>>>(x, TWOK, Wx, En, p_xc, KXC, 0, bx, nullptr, TWOK);
    // embed_count -> xc[:, 128:256]
    sgemm<0><<<dim3(BT / 128, 1), 256>>>(p_cl, TWOK, Wc, En, p_xc, KXC, 128, bc, nullptr, TWOK);
    // pre = xc @ WlP + blP
    sgemm<0><<<dim3(BT / 128, FH / 128), 256>>>(p_xc, KXC, p_WlP, FH, p_pre, FH, 0, p_blP, nullptr, KXC);

    // sequential LSTM scan
    k_lstm<<<128, 256, SMEM_LSTM>>>(Ul);

    // Y = sigmoid(H @ Wo + bo) * q
    sgemm<1><<<dim3(BT / 128, Hh / 128), 256>>>(p_H, Hh, Wo, Hh, p_Y, Hh, 0, bo, q, Hh);
    // out = rowsum(Y)
    k_rowsum<<<BT / 8, 256>>>(out);
}

// round 3
// speedup vs baseline: 1.1418x; 1.1368x over previous
#include <cuda_runtime.h>
#include <math.h>

// Problem dims
#define Bn   64
#define Tn   1024
#define TWOK 512
#define En   128
#define Hh   256
#define FH   1024          // 4*H
#define BT   (Bn*Tn)       // 65536
#define KXC  264           // 2E+1 padded to multiple of 8
#define HROW 288           // skewed h row stride (4 chunks of 72 floats)

// ---------------- packed fp32x2 helpers ----------------
__device__ __forceinline__ void fma2(unsigned long long& acc,
                                     unsigned long long a,
                                     unsigned long long b) {
    asm("fma.rn.f32x2 %0, %1, %2, %0;" : "+l"(acc) : "l"(a), "l"(b));
}
__device__ __forceinline__ float2 unpk(unsigned long long v) {
    float2 r;
    asm("mov.b64 {%0, %1}, %2;" : "=f"(r.x), "=f"(r.y) : "l"(v));
    return r;
}

// ---------------- scratch (static device globals) ----------------
__device__ float g_s[BT];
__device__ float g_Q[Bn * 8 * TWOK];
__device__ float g_Cin[Bn * 8 * TWOK];
__device__ float g_P[Bn * 8];
__device__ float g_cl[(size_t)BT * TWOK];
__device__ float g_xc[(size_t)BT * KXC];
__device__ float g_WlP[KXC * FH];
__device__ float g_blP[FH];
__device__ float g_pre[(size_t)BT * FH];           // [b][t][FH] permuted cols
__device__ float g_H[(size_t)BT * Hh];             // [t][b][256]  <-- time-major!
__device__ float g_Y[(size_t)BT * Hh];             // rows in t*64+b order
__device__ int   g_bar;

// ---------------- tiny kernels ----------------
__global__ void k_reset() { g_bar = 0; }

__global__ void k_sums(const float* __restrict__ x) {
    int row  = blockIdx.x * 8 + (threadIdx.x >> 5);
    int lane = threadIdx.x & 31;
    const float4* xr = (const float4*)(x + (size_t)row * TWOK);
    float s = 0.f;
#pragma unroll
    for (int i = 0; i < 4; i++) {
        float4 v = xr[i * 32 + lane];
        s += v.x + v.y + v.z + v.w;
    }
#pragma unroll
    for (int o = 16; o; o >>= 1) s += __shfl_xor_sync(0xffffffffu, s, o);
    if (!lane) g_s[row] = s;
}

__global__ void k_delta(const float* __restrict__ delta,
                        const float* __restrict__ Wd,
                        const float* __restrict__ bd) {
    int i = blockIdx.x * 256 + threadIdx.x;
    float ed = expf(-(delta[i] * Wd[0] + bd[0]));
    float* xr = g_xc + (size_t)i * KXC;
    xr[256] = ed;
#pragma unroll
    for (int j = 257; j < KXC; j++) xr[j] = 0.f;
}

// ----- segmented count scan: 8 segments x 128 steps -----
__global__ void k_scanA(const float* __restrict__ x) {
    int idx = blockIdx.x * 256 + threadIdx.x;
    int f = idx & 511, seg = (idx >> 9) & 7, b = idx >> 12;
    const float* sp = g_s + b * Tn + seg * 128;
    const float* xp = x + ((size_t)b * Tn + seg * 128) * TWOK + f;
    float c = 0.f;
    for (int tt = 0; tt < 128; tt++)
        c = fmaf(sp[tt], c, xp[(size_t)tt * TWOK]);
    g_Q[idx] = c;
}
__global__ void k_P() {
    int idx = blockIdx.x * 256 + threadIdx.x;
    if (idx >= Bn * 8) return;
    int b = idx >> 3, seg = idx & 7;
    const float* sp = g_s + b * Tn + seg * 128;
    float p = 1.f;
    for (int tt = 0; tt < 128; tt++) p *= sp[tt];
    g_P[idx] = p;
}
__global__ void k_carry() {
    int idx = blockIdx.x * 256 + threadIdx.x;
    int b = idx >> 9, f = idx & 511;
    float c = 0.f;
#pragma unroll
    for (int j = 0; j < 8; j++) {
        int qi = (b * 8 + j) * 512 + f;
        g_Cin[qi] = c;
        c = g_P[b * 8 + j] * c + g_Q[qi];
    }
}
__global__ void k_scanC(const float* __restrict__ x) {
    int idx = blockIdx.x * 256 + threadIdx.x;
    int f = idx & 511, seg = (idx >> 9) & 7, b = idx >> 12;
    const float* sp = g_s + b * Tn + seg * 128;
    const float* xp = x    + ((size_t)b * Tn + seg * 128) * TWOK + f;
    float*       cp = g_cl + ((size_t)b * Tn + seg * 128) * TWOK + f;
    float c = g_Cin[idx];
    for (int tt = 0; tt < 128; tt++) {
        c = fmaf(sp[tt], c, xp[(size_t)tt * TWOK]);
        cp[(size_t)tt * TWOK] = log1pf(c);
    }
}

__global__ void k_wlp(const float* __restrict__ Wl, const float* __restrict__ bl) {
    int i = blockIdx.x * 256 + threadIdx.x;
    if (i >= KXC * FH) return;
    int k = i / FH, jp = i % FH;
    int orig = (jp & 3) * 256 + (jp >> 2);
    g_WlP[i] = (k < 2 * En + 1) ? Wl[k * FH + orig] : 0.f;
    if (k == 0) g_blP[jp] = bl[orig];
}

// ---------------- fp32x2 SGEMM ----------------
// EPI==1: sigmoid * q, rows in t*64+b order -> q index remapped.
template <int EPI>
__global__ void __launch_bounds__(256, 1) sgemm(
    const float* __restrict__ A, int lda,
    const float* __restrict__ Bm, int ldb,
    float* __restrict__ C, int ldc, int coff,
    const float* __restrict__ bias,
    const float* __restrict__ q,
    int K) {
    __shared__ __align__(16) float2 As2[2][4][128];
    __shared__ __align__(16) float2 Bs2[2][4][128];
    const int row0 = blockIdx.x * 128, col0 = blockIdx.y * 128;
    const int tid = threadIdx.x;
    const int ar = tid >> 1, aq = tid & 1;
    const int w = tid >> 5, lane = tid & 31;
    const int bk2 = w >> 1, bc = (w & 1) * 64 + lane * 2;
    const int ty = tid >> 4, tx = tid & 15;

    const float* Ap  = A + (size_t)(row0 + ar) * lda + aq * 4;
    const float* Bp0 = Bm + col0 + bc;

    unsigned long long acc[8][8];
#pragma unroll
    for (int i = 0; i < 8; i++)
#pragma unroll
        for (int j = 0; j < 8; j++) acc[i][j] = 0ull;

    {
        float4 av = *(const float4*)Ap;
        float2 b0 = *(const float2*)(Bp0 + (size_t)(2 * bk2) * ldb);
        float2 b1 = *(const float2*)(Bp0 + (size_t)(2 * bk2 + 1) * ldb);
        As2[0][2 * aq][ar]     = make_float2(av.x, av.y);
        As2[0][2 * aq + 1][ar] = make_float2(av.z, av.w);
        *(float4*)&Bs2[0][bk2][bc] = make_float4(b0.x, b1.x, b0.y, b1.y);
    }
    __syncthreads();

    int buf = 0;
    for (int k0 = 0; k0 < K; k0 += 8) {
        const bool more = (k0 + 8 < K);
        float4 avn; float2 b0n, b1n;
        if (more) {
            avn = *(const float4*)(Ap + k0 + 8);
            b0n = *(const float2*)(Bp0 + (size_t)(k0 + 8 + 2 * bk2) * ldb);
            b1n = *(const float2*)(Bp0 + (size_t)(k0 + 8 + 2 * bk2 + 1) * ldb);
        }
#pragma unroll
        for (int kk2 = 0; kk2 < 4; kk2++) {
            ulonglong2 a01 = *(const ulonglong2*)&As2[buf][kk2][ty * 8];
            ulonglong2 a23 = *(const ulonglong2*)&As2[buf][kk2][ty * 8 + 2];
            ulonglong2 a45 = *(const ulonglong2*)&As2[buf][kk2][ty * 8 + 4];
            ulonglong2 a67 = *(const ulonglong2*)&As2[buf][kk2][ty * 8 + 6];
            ulonglong2 b01 = *(const ulonglong2*)&Bs2[buf][kk2][tx * 8];
            ulonglong2 b23 = *(const ulonglong2*)&Bs2[buf][kk2][tx * 8 + 2];
            ulonglong2 b45 = *(const ulonglong2*)&Bs2[buf][kk2][tx * 8 + 4];
            ulonglong2 b67 = *(const ulonglong2*)&Bs2[buf][kk2][tx * 8 + 6];
            unsigned long long aa[8] = {a01.x, a01.y, a23.x, a23.y,
                                        a45.x, a45.y, a67.x, a67.y};
            unsigned long long bb[8] = {b01.x, b01.y, b23.x, b23.y,
                                        b45.x, b45.y, b67.x, b67.y};
#pragma unroll
            for (int i = 0; i < 8; i++)
#pragma unroll
                for (int j = 0; j < 8; j++) fma2(acc[i][j], aa[i], bb[j]);
        }
        if (more) {
            As2[buf ^ 1][2 * aq][ar]     = make_float2(avn.x, avn.y);
            As2[buf ^ 1][2 * aq + 1][ar] = make_float2(avn.z, avn.w);
            *(float4*)&Bs2[buf ^ 1][bk2][bc] = make_float4(b0n.x, b1n.x, b0n.y, b1n.y);
        }
        __syncthreads();
        buf ^= 1;
    }

#pragma unroll
    for (int i = 0; i < 8; i++) {
        size_t r = (size_t)row0 + ty * 8 + i;
#pragma unroll
        for (int j = 0; j < 8; j++) {
            int c = col0 + tx * 8 + j;
            float2 p = unpk(acc[i][j]);
            float v = p.x + p.y + bias[c];
            if (EPI == 1) {
                // rows are t*64+b; q is [b][t][256]
                size_t qr = ((size_t)(r & 63) << 10) + (r >> 6);
                v = q[qr * 256 + c] / (1.f + expf(-v));
            }
            C[r * ldc + coff + c] = v;
        }
    }
}

// ---------------- persistent LSTM scan ----------------
// 128 CTAs; CTA g owns permuted gate cols [8g, 8g+8) (units 2g, 2g+1).
// Lane = (col c in [0,8), k-chunk kc in [0,4)); Ul column chunk cached in regs.
// Warp w handles batches [8w, 8w+8). h staged in smem with 72-float chunk skew
// so the 4 kc-chunks occupy disjoint bank regions -> broadcast LDS, 1 phase.
__global__ void __launch_bounds__(256, 1) k_lstm(const float* __restrict__ Ul) {
    extern __shared__ float sm[];
    float* hs = sm;                    // 64 * HROW
    float* zs = sm + 64 * HROW;        // 64 * 8

    const int g = blockIdx.x, tid = threadIdx.x;
    const int w = tid >> 5, lane = tid & 31;
    const int c = lane & 7, kc = lane >> 3;
    const int k0 = kc * 64;
    const int orig = (c & 3) * 256 + 2 * g + (c >> 2);   // original Ul column

    // ---- cache Ul chunk in registers: 64 k-values = 32 packed pairs ----
    unsigned long long ureg[32];
#pragma unroll
    for (int i = 0; i < 32; i++) {
        float u0 = Ul[(size_t)(k0 + 2 * i) * FH + orig];
        float u1 = Ul[(size_t)(k0 + 2 * i + 1) * FH + orig];
        asm("mov.b64 %0, {%1, %2};" : "=l"(ureg[i]) : "f"(u0), "f"(u1));
    }

    const int gb = tid >> 1, gu = tid & 1;   // gates mapping (tid < 128)
    float cst = 0.f;
    int* barp = &g_bar;

    for (int t = 0; t < Tn; t++) {
        // ---- stage h_{t-1} into skewed smem ----
        if (t == 0) {
#pragma unroll
            for (int j = 0; j < 16; j++) {
                int idx = tid + 256 * j;
                int b = idx >> 6, k4 = idx & 63;
                int col = k4 * 4;
                *(float4*)&hs[b * HROW + (col >> 6) * 72 + (col & 63)] =
                    make_float4(0.f, 0.f, 0.f, 0.f);
            }
        } else {
            const float* src = g_H + (size_t)(t - 1) * (Bn * Hh);
#pragma unroll
            for (int j = 0; j < 16; j++) {
                int idx = tid + 256 * j;
                int b = idx >> 6, k4 = idx & 63;
                float4 v = __ldcg((const float4*)(src + b * Hh + k4 * 4));
                int col = k4 * 4;
                *(float4*)&hs[b * HROW + (col >> 6) * 72 + (col & 63)] = v;
            }
        }
        // pre loads (only kc==0 lanes need them), overlap with staging
        float prer[8];
        if (kc == 0) {
#pragma unroll
            for (int bi = 0; bi < 8; bi++)
                prer[bi] = g_pre[((size_t)(8 * w + bi) * Tn + t) * FH + 8 * g + c];
        }
        __syncthreads();

        // ---- z-partials: 8 batches x 1 col x 64 k, u from regs, h broadcast ----
#pragma unroll
        for (int bi = 0; bi < 8; bi++) {
            const ulonglong2* hrow =
                (const ulonglong2*)&hs[(8 * w + bi) * HROW + kc * 72];
            unsigned long long a = 0ull;
#pragma unroll
            for (int i = 0; i < 16; i++) {
                ulonglong2 hv = hrow[i];
                fma2(a, ureg[2 * i],     hv.x);
                fma2(a, ureg[2 * i + 1], hv.y);
            }
            float2 p = unpk(a);
            float v = p.x + p.y;
            v += __shfl_xor_sync(0xffffffffu, v, 8);
            v += __shfl_xor_sync(0xffffffffu, v, 16);
            if (kc == 0) zs[(8 * w + bi) * 8 + c] = v + prer[bi];
        }
        __syncthreads();

        // ---- gates + state update (128 threads: one (batch, unit) each) ----
        if (tid < 128) {
            float zi = zs[gb * 8 + gu * 4 + 0];
            float zf = zs[gb * 8 + gu * 4 + 1];
            float zg = zs[gb * 8 + gu * 4 + 2];
            float zo = zs[gb * 8 + gu * 4 + 3];
            float ig = 1.f / (1.f + expf(-zi));
            float fg = 1.f / (1.f + expf(-zf));
            float gg = tanhf(zg);
            float og = 1.f / (1.f + expf(-zo));
            cst = fg * cst + ig * gg;
            float h = og * tanhf(cst);
            __stcg(&g_H[(size_t)t * (Bn * Hh) + gb * Hh + 2 * g + gu], h);
        }
        __syncthreads();

        // ---- grid barrier: release arrival + acquire spin ----
        if (tid == 0) {
            asm volatile("red.release.gpu.global.add.s32 [%0], 1;"
                         :: "l"(barp) : "memory");
            int target = 128 * (t + 1), v;
            do {
                asm volatile("ld.acquire.gpu.global.b32 %0, [%1];"
                             : "=r"(v) : "l"(barp) : "memory");
            } while (v < target);
        }
        __syncthreads();
    }
}

// rows of g_Y are in t*64+b order; out is [b][t]
__global__ void k_rowsum(float* __restrict__ out) {
    int row  = blockIdx.x * 8 + (threadIdx.x >> 5);
    int lane = threadIdx.x & 31;
    const float4* yr = (const float4*)(g_Y + (size_t)row * Hh);
    float4 a = yr[lane], b = yr[lane + 32];
    float s = a.x + a.y + a.z + a.w + b.x + b.y + b.z + b.w;
#pragma unroll
    for (int o = 16; o; o >>= 1) s += __shfl_xor_sync(0xffffffffu, s, o);
    if (!lane) out[(row & 63) * Tn + (row >> 6)] = s;
}

// ---------------- launch ----------------
extern "C" void kernel_launch(void* const* d_in, const int* in_sizes, int n_in,
                              void* d_out, int out_size) {
    const float* x     = (const float*)d_in[0];
    const float* delta = (const float*)d_in[1];
    const float* q     = (const float*)d_in[2];
    const float* Wx    = (const float*)d_in[3];
    const float* bx    = (const float*)d_in[4];
    const float* Wc    = (const float*)d_in[5];
    const float* bc    = (const float*)d_in[6];
    const float* Wd    = (const float*)d_in[7];
    const float* bd    = (const float*)d_in[8];
    const float* Wl    = (const float*)d_in[9];
    const float* Ul    = (const float*)d_in[10];
    const float* bl    = (const float*)d_in[11];
    const float* Wo    = (const float*)d_in[12];
    const float* bo    = (const float*)d_in[13];
    float* out = (float*)d_out;

    const int SMEM_LSTM = (64 * HROW + 64 * 8) * 4;   // 75776 B
    cudaFuncSetAttribute(k_lstm, cudaFuncAttributeMaxDynamicSharedMemorySize, SMEM_LSTM);

    float *p_xc, *p_cl, *p_pre, *p_H, *p_Y, *p_WlP, *p_blP;
    cudaGetSymbolAddress((void**)&p_xc,  g_xc);
    cudaGetSymbolAddress((void**)&p_cl,  g_cl);
    cudaGetSymbolAddress((void**)&p_pre, g_pre);
    cudaGetSymbolAddress((void**)&p_H,   g_H);
    cudaGetSymbolAddress((void**)&p_Y,   g_Y);
    cudaGetSymbolAddress((void**)&p_WlP, g_WlP);
    cudaGetSymbolAddress((void**)&p_blP, g_blP);

    k_reset<<<1, 1>>>();
    k_sums<<<BT / 8, 256>>>(x);
    k_delta<<<BT / 256, 256>>>(delta, Wd, bd);
    k_wlp<<<(KXC * FH + 255) / 256, 256>>>(Wl, bl);

    // segmented count scan
    k_scanA<<<1024, 256>>>(x);
    k_P<<<2, 256>>>();
    k_carry<<<128, 256>>>();
    k_scanC<<<1024, 256>>>(x);

    // embed_x -> xc[:, 0:128]
    sgemm<0><<<dim3(BT / 128, 1), 256>>>(x, TWOK, Wx, En, p_xc, KXC, 0, bx, nullptr, TWOK);
    // embed_count -> xc[:, 128:256]
    sgemm<0><<<dim3(BT / 128, 1), 256>>>(p_cl, TWOK, Wc, En, p_xc, KXC, 128, bc, nullptr, TWOK);
    // pre = xc @ WlP + blP
    sgemm<0><<<dim3(BT / 128, FH / 128), 256>>>(p_xc, KXC, p_WlP, FH, p_pre, FH, 0, p_blP, nullptr, KXC);

    // sequential LSTM scan (persistent, 128 co-resident CTAs)
    k_lstm<<<128, 256, SMEM_LSTM>>>(Ul);

    // Y = sigmoid(H @ Wo + bo) * q   (rows in t*64+b order)
    sgemm<1><<<dim3(BT / 128, Hh / 128), 256>>>(p_H, Hh, Wo, Hh, p_Y, Hh, 0, bo, q, Hh);
    // out = rowsum(Y) with row remap
    k_rowsum<<<BT / 8, 256>>>(out);
}